// round 12
// baseline (speedup 1.0000x reference)
#include <cuda_runtime.h>
#include <cuda_fp16.h>
#include <cstdint>

// Problem constants
constexpr int BB = 256;    // batch
constexpr int KK = 8;      // in_size
constexpr int II = 1152;   // in_node_num
constexpr int NN = 10;     // num_node
constexpr int OO = 16;     // node_size
constexpr int IK = II * KK;   // 9216
constexpr int NO = NN * OO;   // 160
constexpr int KC = 36;        // split-K chunks for s-GEMM (9216/256)
constexpr int KCW = IK / KC;  // 256

// Static device scratch (~24 MB total, L2-resident)
__device__ __half g_xh [BB * IK];     // xh[b][i*8+k]
__device__ __half g_xhT[IK * BB];     // xhT[i*8+k][b]
__device__ float  g_Wps[II * NO * KK];// Wps[i][n][o][k] = 0.03*W
__device__ __half g_A  [NO * IK];     // A[n*16+o][i*8+k] = c * Wps
__device__ float  g_sp [KC][BB * NO]; // split-K partials
__device__ __half g_vT [NO * BB];     // vT[no][b]
__device__ float  g_bij[II * NN];
__device__ float  g_uvp[2][II * NN];  // uv partials per batch-half

// ---------------------------------------------------------------------------
__device__ __forceinline__ void mma16816(float* c, uint32_t a0, uint32_t a1,
                                         uint32_t a2, uint32_t a3,
                                         uint32_t b0, uint32_t b1) {
    asm volatile(
        "mma.sync.aligned.m16n8k16.row.col.f32.f16.f16.f32 "
        "{%0,%1,%2,%3}, {%4,%5,%6,%7}, {%8,%9}, {%0,%1,%2,%3};"
        : "+f"(c[0]), "+f"(c[1]), "+f"(c[2]), "+f"(c[3])
        : "r"(a0), "r"(a1), "r"(a2), "r"(a3), "r"(b0), "r"(b1));
}

__device__ __forceinline__ void ldsm_x4(uint32_t* r, uint32_t addr) {
    asm volatile(
        "ldmatrix.sync.aligned.m8n8.x4.shared.b16 {%0,%1,%2,%3}, [%4];"
        : "=r"(r[0]), "=r"(r[1]), "=r"(r[2]), "=r"(r[3]) : "r"(addr));
}

__device__ __forceinline__ uint32_t smem_u32(const void* p) {
    return (uint32_t)__cvta_generic_to_shared(p);
}

// ---------------------------------------------------------------------------
// P: fused prep. Blocks [0,288): pack x -> xh, xhT. Blocks [288,1008): Wps + A0.
__global__ __launch_bounds__(256) void k_prep(const float* __restrict__ x,
                                              const float* __restrict__ W) {
    __shared__ float tf[32][32][9];   // [b][i][k], pad 9
    int t = threadIdx.x;
    if (blockIdx.x < 288) {
        int tile = blockIdx.x;
        int i0 = (tile % 36) * 32, b0 = (tile / 36) * 32;
        int kk = t >> 5, il = t & 31;
#pragma unroll
        for (int j = 0; j < 32; j++)
            tf[j][il][kk] = x[((size_t)(b0 + j) * KK + kk) * II + i0 + il];
        __syncthreads();
#pragma unroll
        for (int jj = 0; jj < 4; jj++) {
            int s = jj * 256 + t;
            int bl = s >> 5, u = s & 31;
            __half h[8];
#pragma unroll
            for (int k = 0; k < 8; k++) h[k] = __float2half_rn(tf[bl][u][k]);
            *reinterpret_cast<uint4*>(&g_xh[(size_t)(b0 + bl) * IK + (i0 + u) * 8]) =
                *reinterpret_cast<const uint4*>(h);
        }
#pragma unroll
        for (int jj = 0; jj < 4; jj++) {
            int s = jj * 256 + t;
            int row = s >> 2, w = s & 3;
            int il2 = row >> 3, k = row & 7;
            __half h[8];
#pragma unroll
            for (int bb = 0; bb < 8; bb++) h[bb] = __float2half_rn(tf[w * 8 + bb][il2][k]);
            *reinterpret_cast<uint4*>(&g_xhT[(size_t)((i0 + il2) * 8 + k) * BB + b0 + w * 8]) =
                *reinterpret_cast<const uint4*>(h);
        }
    } else {
        int tid = (blockIdx.x - 288) * 256 + t;   // (i*160 + no)
        if (tid >= II * NO) return;
        int i = tid / NO, no = tid % NO;
        float4 w0 = *reinterpret_cast<const float4*>(&W[(size_t)tid * 8]);
        float4 w1 = *reinterpret_cast<const float4*>(&W[(size_t)tid * 8 + 4]);
        float s = 0.03f;
        float4 p0 = make_float4(s * w0.x, s * w0.y, s * w0.z, s * w0.w);
        float4 p1 = make_float4(s * w1.x, s * w1.y, s * w1.z, s * w1.w);
        *reinterpret_cast<float4*>(&g_Wps[(size_t)tid * 8]) = p0;
        *reinterpret_cast<float4*>(&g_Wps[(size_t)tid * 8 + 4]) = p1;
        __half h[8];
        h[0] = __float2half_rn(0.1f * p0.x); h[1] = __float2half_rn(0.1f * p0.y);
        h[2] = __float2half_rn(0.1f * p0.z); h[3] = __float2half_rn(0.1f * p0.w);
        h[4] = __float2half_rn(0.1f * p1.x); h[5] = __float2half_rn(0.1f * p1.y);
        h[6] = __float2half_rn(0.1f * p1.z); h[7] = __float2half_rn(0.1f * p1.w);
        *reinterpret_cast<uint4*>(&g_A[(size_t)no * IK + i * 8]) =
            *reinterpret_cast<const uint4*>(h);
    }
}

// ---------------------------------------------------------------------------
// G1: s-GEMM, split-K, pipelined, ldmatrix. grid 144 = 4 b-tiles x 36 kc.
__global__ __launch_bounds__(256, 2) void k_sgemm() {
    __shared__ __half Asm[64][72];
    __shared__ __half Bsm[160][72];
    int t = threadIdx.x;
    int bm = blockIdx.x & 3, kc = blockIdx.x >> 2;
    int b0 = bm * 64, kbase = kc * KCW;
    int warp = t >> 5, lane = t & 31;
    int wm = warp >> 1, wn = warp & 1;
    int gr = lane >> 2, tc = lane & 3;

    int arow[2], acol[2], brow[5], bcol[5];
#pragma unroll
    for (int j = 0; j < 2; j++) { int s = j * 256 + t; arow[j] = s >> 3; acol[j] = s & 7; }
#pragma unroll
    for (int j = 0; j < 5; j++) { int s = j * 256 + t; brow[j] = s >> 3; bcol[j] = s & 7; }

    int T = lane >> 3, Lr = lane & 7;
    uint32_t aAddr = smem_u32(&Asm[wm * 16 + (T & 1) * 8 + Lr][(T >> 1) * 8]);
    uint32_t bAddr[5];
#pragma unroll
    for (int f2 = 0; f2 < 5; f2++)
        bAddr[f2] = smem_u32(&Bsm[wn * 80 + f2 * 16 + (T >> 1) * 8 + Lr][(T & 1) * 8]);

    float acc[10][4];
#pragma unroll
    for (int f = 0; f < 10; f++)
#pragma unroll
        for (int q = 0; q < 4; q++) acc[f][q] = 0.0f;

    uint4 pa[2], pb[5];
#pragma unroll
    for (int j = 0; j < 2; j++)
        pa[j] = *reinterpret_cast<const uint4*>(&g_xh[(size_t)(b0 + arow[j]) * IK + kbase + acol[j] * 8]);
#pragma unroll
    for (int j = 0; j < 5; j++)
        pb[j] = *reinterpret_cast<const uint4*>(&g_A[(size_t)brow[j] * IK + kbase + bcol[j] * 8]);

    for (int st = 0; st < 4; st++) {
        if (st) __syncthreads();
#pragma unroll
        for (int j = 0; j < 2; j++)
            *reinterpret_cast<uint4*>(&Asm[arow[j]][acol[j] * 8]) = pa[j];
#pragma unroll
        for (int j = 0; j < 5; j++)
            *reinterpret_cast<uint4*>(&Bsm[brow[j]][bcol[j] * 8]) = pb[j];
        __syncthreads();
        if (st < 3) {
            int ks = kbase + (st + 1) * 64;
#pragma unroll
            for (int j = 0; j < 2; j++)
                pa[j] = *reinterpret_cast<const uint4*>(&g_xh[(size_t)(b0 + arow[j]) * IK + ks + acol[j] * 8]);
#pragma unroll
            for (int j = 0; j < 5; j++)
                pb[j] = *reinterpret_cast<const uint4*>(&g_A[(size_t)brow[j] * IK + ks + bcol[j] * 8]);
        }
#pragma unroll
        for (int kk = 0; kk < 4; kk++) {
            uint32_t coff = kk * 32;
            uint32_t a[4];
            ldsm_x4(a, aAddr + coff);
#pragma unroll
            for (int f2 = 0; f2 < 5; f2++) {
                uint32_t b[4];
                ldsm_x4(b, bAddr[f2] + coff);
                mma16816(acc[2 * f2],     a[0], a[1], a[2], a[3], b[0], b[1]);
                mma16816(acc[2 * f2 + 1], a[0], a[1], a[2], a[3], b[2], b[3]);
            }
        }
    }
#pragma unroll
    for (int f = 0; f < 10; f++) {
        int no = wn * 80 + f * 8 + 2 * tc;
        int r0 = b0 + wm * 16 + gr;
        *reinterpret_cast<float2*>(&g_sp[kc][(size_t)r0 * NO + no]) =
            make_float2(acc[f][0], acc[f][1]);
        *reinterpret_cast<float2*>(&g_sp[kc][(size_t)(r0 + 8) * NO + no]) =
            make_float2(acc[f][2], acc[f][3]);
    }
}

// ---------------------------------------------------------------------------
// G2: reduce split-K + squash, 4-way parallel over kc. grid 640 x 256.
__global__ __launch_bounds__(256) void k_squash(float* __restrict__ out, int last) {
    __shared__ float red[4][64];
    int t = threadIdx.x;
    int g = t >> 6, sl = t & 63;
    int slot = blockIdx.x * 64 + sl;

    float ps = 0.0f;
#pragma unroll
    for (int q = 0; q < 9; q++) ps += g_sp[g * 9 + q][slot];
    red[g][sl] = ps;
    __syncthreads();

    if (t < 64) {
        float s = (red[0][sl] + red[1][sl]) + (red[2][sl] + red[3][sl]);
        float m = s * s;
        m += __shfl_xor_sync(0xffffffffu, m, 1);
        m += __shfl_xor_sync(0xffffffffu, m, 2);
        m += __shfl_xor_sync(0xffffffffu, m, 4);
        m += __shfl_xor_sync(0xffffffffu, m, 8);
        float v = s * (sqrtf(m) / (1.0f + m));
        if (last) {
            out[slot] = v;
        } else {
            int b = slot / NO, no = slot % NO;
            g_vT[(size_t)no * BB + b] = __float2half_rn(v);
        }
    }
}

// ---------------------------------------------------------------------------
// G3a: uv-GEMM over one batch-half. grid 288 = 144 ik-tiles x 2 b-halves.
// Writes Wps-weighted partial agreement to g_uvp[bh][i][n].
__global__ __launch_bounds__(256, 2) void k_uv_gemm() {
    __shared__ __half Asm[64][72];
    __shared__ __half Bsm[160][72];
    int t = threadIdx.x;
    int tileid = blockIdx.x >> 1, bh = blockIdx.x & 1;
    int iblk0 = tileid * 8;
    int ikbase = tileid * 64;
    int bs0 = bh * 128;
    int warp = t >> 5, lane = t & 31;
    int wm = warp >> 1, wn = warp & 1;
    int gr = lane >> 2, tc = lane & 3;

    int arow[2], acol[2], brow[5], bcol[5];
#pragma unroll
    for (int j = 0; j < 2; j++) { int s = j * 256 + t; arow[j] = s >> 3; acol[j] = s & 7; }
#pragma unroll
    for (int j = 0; j < 5; j++) { int s = j * 256 + t; brow[j] = s >> 3; bcol[j] = s & 7; }

    int T = lane >> 3, Lr = lane & 7;
    uint32_t aAddr = smem_u32(&Asm[wm * 16 + (T & 1) * 8 + Lr][(T >> 1) * 8]);
    uint32_t bAddr[5];
#pragma unroll
    for (int f2 = 0; f2 < 5; f2++)
        bAddr[f2] = smem_u32(&Bsm[wn * 80 + f2 * 16 + (T >> 1) * 8 + Lr][(T & 1) * 8]);

    float acc[10][4];
#pragma unroll
    for (int f = 0; f < 10; f++)
#pragma unroll
        for (int q = 0; q < 4; q++) acc[f][q] = 0.0f;

    uint4 pa[2], pb[5];
#pragma unroll
    for (int j = 0; j < 2; j++)
        pa[j] = *reinterpret_cast<const uint4*>(&g_xhT[(size_t)(ikbase + arow[j]) * BB + bs0 + acol[j] * 8]);
#pragma unroll
    for (int j = 0; j < 5; j++)
        pb[j] = *reinterpret_cast<const uint4*>(&g_vT[(size_t)brow[j] * BB + bs0 + bcol[j] * 8]);

    for (int st = 0; st < 2; st++) {
        if (st) __syncthreads();
#pragma unroll
        for (int j = 0; j < 2; j++)
            *reinterpret_cast<uint4*>(&Asm[arow[j]][acol[j] * 8]) = pa[j];
#pragma unroll
        for (int j = 0; j < 5; j++)
            *reinterpret_cast<uint4*>(&Bsm[brow[j]][bcol[j] * 8]) = pb[j];
        __syncthreads();
        if (st < 1) {
            int bs = bs0 + 64;
#pragma unroll
            for (int j = 0; j < 2; j++)
                pa[j] = *reinterpret_cast<const uint4*>(&g_xhT[(size_t)(ikbase + arow[j]) * BB + bs + acol[j] * 8]);
#pragma unroll
            for (int j = 0; j < 5; j++)
                pb[j] = *reinterpret_cast<const uint4*>(&g_vT[(size_t)brow[j] * BB + bs + bcol[j] * 8]);
        }
#pragma unroll
        for (int kk = 0; kk < 4; kk++) {
            uint32_t coff = kk * 32;
            uint32_t a[4];
            ldsm_x4(a, aAddr + coff);
#pragma unroll
            for (int f2 = 0; f2 < 5; f2++) {
                uint32_t b[4];
                ldsm_x4(b, bAddr[f2] + coff);
                mma16816(acc[2 * f2],     a[0], a[1], a[2], a[3], b[0], b[1]);
                mma16816(acc[2 * f2 + 1], a[0], a[1], a[2], a[3], b[2], b[3]);
            }
        }
    }

    // weight C frags with Wps, reduce over (k,o), write partials
    int i0g = iblk0 + wm * 2;
    int i1g = i0g + 1;
    float p[2][5];
#pragma unroll
    for (int il = 0; il < 2; il++)
#pragma unroll
        for (int nl = 0; nl < 5; nl++) p[il][nl] = 0.0f;

#pragma unroll
    for (int f = 0; f < 10; f++) {
        int no = wn * 80 + f * 8 + 2 * tc;
        int n = no >> 4, o = no & 15;
        float w00 = g_Wps[(((size_t)i0g * NN + n) * OO + o) * KK + gr];
        float w01 = g_Wps[(((size_t)i0g * NN + n) * OO + o + 1) * KK + gr];
        float w10 = g_Wps[(((size_t)i1g * NN + n) * OO + o) * KK + gr];
        float w11 = g_Wps[(((size_t)i1g * NN + n) * OO + o + 1) * KK + gr];
        int nl = f >> 1;
        p[0][nl] += acc[f][0] * w00 + acc[f][1] * w01;
        p[1][nl] += acc[f][2] * w10 + acc[f][3] * w11;
    }
#pragma unroll
    for (int il = 0; il < 2; il++)
#pragma unroll
        for (int nl = 0; nl < 5; nl++) {
            float v = p[il][nl];
#pragma unroll
            for (int off = 16; off > 0; off >>= 1)
                v += __shfl_xor_sync(0xffffffffu, v, off);
            if (lane == 0)
                g_uvp[bh][(iblk0 + wm * 2 + il) * NN + wn * 5 + nl] = v;
        }
}

// ---------------------------------------------------------------------------
// G3b: combine uv halves, routing update (softmax), A-build. grid 144 x 256.
__global__ __launch_bounds__(256) void k_uv_finish(int first) {
    __shared__ float cs[8][10];
    int t = threadIdx.x;
    int iblk0 = blockIdx.x * 8;
    int ikbase = blockIdx.x * 64;

    if (t < 8) {
        int i = iblk0 + t;
        float bv[NN];
        float mx = -1e30f;
#pragma unroll
        for (int n = 0; n < NN; n++) {
            float uv = g_uvp[0][i * NN + n] + g_uvp[1][i * NN + n];
            float bp = first ? 0.0f : g_bij[i * NN + n];
            bv[n] = bp + uv * (1.0f / BB);
            g_bij[i * NN + n] = bv[n];
            mx = fmaxf(mx, bv[n]);
        }
        float sum = 0.0f;
#pragma unroll
        for (int n = 0; n < NN; n++) { bv[n] = __expf(bv[n] - mx); sum += bv[n]; }
        float inv = 1.0f / sum;
#pragma unroll
        for (int n = 0; n < NN; n++) cs[t][n] = bv[n] * inv;
    }
    __syncthreads();

    // A-build: A[no][ikbase..+64) = c[i,n]*Wps
#pragma unroll
    for (int j = 0; j < 20; j++) {
        int s = j * 256 + t;            // 5120 half2 slots
        int no = s >> 5, cp = s & 31;
        int k2 = cp * 2;
        int il = cp >> 2, k = k2 & 7;
        int n = no >> 4, o = no & 15;
        float2 wv = *reinterpret_cast<const float2*>(
            &g_Wps[(((size_t)(iblk0 + il) * NN + n) * OO + o) * KK + k]);
        float cc = cs[il][n];
        __half2 h = __floats2half2_rn(cc * wv.x, cc * wv.y);
        *reinterpret_cast<__half2*>(&g_A[(size_t)no * IK + ikbase + k2]) = h;
    }
}

// ---------------------------------------------------------------------------
extern "C" void kernel_launch(void* const* d_in, const int* in_sizes, int n_in,
                              void* d_out, int out_size) {
    const float* x = (const float*)d_in[0];   // (256, 8, 1152) fp32
    const float* W = (const float*)d_in[1];   // (1, 1152, 10, 16, 8) fp32
    float* out = (float*)d_out;               // (256, 10, 16, 1) fp32

    k_prep<<<288 + (II * NO + 255) / 256, 256>>>(x, W);

    // iter 1 (c = 0.1 baked into A0)
    k_sgemm<<<4 * KC, 256>>>();
    k_squash<<<BB * NO / 64, 256>>>(out, 0);
    k_uv_gemm<<<288, 256>>>();
    k_uv_finish<<<144, 256>>>(1);
    // iter 2
    k_sgemm<<<4 * KC, 256>>>();
    k_squash<<<BB * NO / 64, 256>>>(out, 0);
    k_uv_gemm<<<288, 256>>>();
    k_uv_finish<<<144, 256>>>(0);
    // iter 3
    k_sgemm<<<4 * KC, 256>>>();
    k_squash<<<BB * NO / 64, 256>>>(out, 1);
}

// round 13
// speedup vs baseline: 1.0684x; 1.0684x over previous
#include <cuda_runtime.h>
#include <cuda_fp16.h>
#include <cstdint>

// Problem constants
constexpr int BB = 256;    // batch
constexpr int KK = 8;      // in_size
constexpr int II = 1152;   // in_node_num
constexpr int NN = 10;     // num_node
constexpr int OO = 16;     // node_size
constexpr int IK = II * KK;   // 9216
constexpr int NO = NN * OO;   // 160
constexpr int KC = 36;        // split-K chunks for s-GEMM (9216/256)
constexpr int KCW = IK / KC;  // 256

// Static device scratch (~30 MB total, L2-resident)
__device__ __half g_xh  [BB * IK];      // xh[b][i*8+k]
__device__ __half g_xhT [IK * BB];      // xhT[i*8+k][b]
__device__ float  g_Wps [II * NO * KK]; // Wps[i][n][o][k] = 0.03*W
__device__ float  g_WpsT[II * KK * NO]; // WpsT[i][k][n*16+o] (uv epilogue)
__device__ __half g_A   [NO * IK];      // A[n*16+o][i*8+k] = c * Wps
__device__ float  g_sp  [KC][BB * NO];  // split-K partials
__device__ __half g_vT  [NO * BB];      // vT[no][b]
__device__ float  g_bij [II * NN];

// ---------------------------------------------------------------------------
__device__ __forceinline__ void mma16816(float* c, uint32_t a0, uint32_t a1,
                                         uint32_t a2, uint32_t a3,
                                         uint32_t b0, uint32_t b1) {
    asm volatile(
        "mma.sync.aligned.m16n8k16.row.col.f32.f16.f16.f32 "
        "{%0,%1,%2,%3}, {%4,%5,%6,%7}, {%8,%9}, {%0,%1,%2,%3};"
        : "+f"(c[0]), "+f"(c[1]), "+f"(c[2]), "+f"(c[3])
        : "r"(a0), "r"(a1), "r"(a2), "r"(a3), "r"(b0), "r"(b1));
}

__device__ __forceinline__ void ldsm_x4(uint32_t* r, uint32_t addr) {
    asm volatile(
        "ldmatrix.sync.aligned.m8n8.x4.shared.b16 {%0,%1,%2,%3}, [%4];"
        : "=r"(r[0]), "=r"(r[1]), "=r"(r[2]), "=r"(r[3]) : "r"(addr));
}

__device__ __forceinline__ uint32_t smem_u32(const void* p) {
    return (uint32_t)__cvta_generic_to_shared(p);
}

// ---------------------------------------------------------------------------
// P: fused prep. Blocks [0,288): pack x -> xh, xhT. Blocks [288,1008): Wps + A0.
__global__ __launch_bounds__(256) void k_prep(const float* __restrict__ x,
                                              const float* __restrict__ W) {
    __shared__ float tf[32][32][9];   // [b][i][k], pad 9
    int t = threadIdx.x;
    if (blockIdx.x < 288) {
        int tile = blockIdx.x;
        int i0 = (tile % 36) * 32, b0 = (tile / 36) * 32;
        int kk = t >> 5, il = t & 31;
#pragma unroll
        for (int j = 0; j < 32; j++)
            tf[j][il][kk] = x[((size_t)(b0 + j) * KK + kk) * II + i0 + il];
        __syncthreads();
#pragma unroll
        for (int jj = 0; jj < 4; jj++) {
            int s = jj * 256 + t;
            int bl = s >> 5, u = s & 31;
            __half h[8];
#pragma unroll
            for (int k = 0; k < 8; k++) h[k] = __float2half_rn(tf[bl][u][k]);
            *reinterpret_cast<uint4*>(&g_xh[(size_t)(b0 + bl) * IK + (i0 + u) * 8]) =
                *reinterpret_cast<const uint4*>(h);
        }
#pragma unroll
        for (int jj = 0; jj < 4; jj++) {
            int s = jj * 256 + t;
            int row = s >> 2, w = s & 3;
            int il2 = row >> 3, k = row & 7;
            __half h[8];
#pragma unroll
            for (int bb = 0; bb < 8; bb++) h[bb] = __float2half_rn(tf[w * 8 + bb][il2][k]);
            *reinterpret_cast<uint4*>(&g_xhT[(size_t)((i0 + il2) * 8 + k) * BB + b0 + w * 8]) =
                *reinterpret_cast<const uint4*>(h);
        }
    } else {
        int tid = (blockIdx.x - 288) * 256 + t;   // (i*160 + no)
        if (tid >= II * NO) return;
        int i = tid / NO, no = tid % NO;
        float4 w0 = *reinterpret_cast<const float4*>(&W[(size_t)tid * 8]);
        float4 w1 = *reinterpret_cast<const float4*>(&W[(size_t)tid * 8 + 4]);
        float s = 0.03f;
        float p[8] = { s*w0.x, s*w0.y, s*w0.z, s*w0.w, s*w1.x, s*w1.y, s*w1.z, s*w1.w };
        *reinterpret_cast<float4*>(&g_Wps[(size_t)tid * 8])     = make_float4(p[0], p[1], p[2], p[3]);
        *reinterpret_cast<float4*>(&g_Wps[(size_t)tid * 8 + 4]) = make_float4(p[4], p[5], p[6], p[7]);
#pragma unroll
        for (int k = 0; k < 8; k++)
            g_WpsT[((size_t)i * KK + k) * NO + no] = p[k];
        __half h[8];
#pragma unroll
        for (int k = 0; k < 8; k++) h[k] = __float2half_rn(0.1f * p[k]);
        *reinterpret_cast<uint4*>(&g_A[(size_t)no * IK + i * 8]) =
            *reinterpret_cast<const uint4*>(h);
    }
}

// ---------------------------------------------------------------------------
// G1: s-GEMM, split-K, pipelined, ldmatrix. grid 144 = 4 b-tiles x 36 kc.
__global__ __launch_bounds__(256) void k_sgemm() {
    __shared__ __half Asm[64][72];
    __shared__ __half Bsm[160][72];
    int t = threadIdx.x;
    int bm = blockIdx.x & 3, kc = blockIdx.x >> 2;
    int b0 = bm * 64, kbase = kc * KCW;
    int warp = t >> 5, lane = t & 31;
    int wm = warp >> 1, wn = warp & 1;
    int gr = lane >> 2, tc = lane & 3;

    int arow[2], acol[2], brow[5], bcol[5];
#pragma unroll
    for (int j = 0; j < 2; j++) { int s = j * 256 + t; arow[j] = s >> 3; acol[j] = s & 7; }
#pragma unroll
    for (int j = 0; j < 5; j++) { int s = j * 256 + t; brow[j] = s >> 3; bcol[j] = s & 7; }

    int T = lane >> 3, Lr = lane & 7;
    uint32_t aAddr = smem_u32(&Asm[wm * 16 + (T & 1) * 8 + Lr][(T >> 1) * 8]);
    uint32_t bAddr[5];
#pragma unroll
    for (int f2 = 0; f2 < 5; f2++)
        bAddr[f2] = smem_u32(&Bsm[wn * 80 + f2 * 16 + (T >> 1) * 8 + Lr][(T & 1) * 8]);

    float acc[10][4];
#pragma unroll
    for (int f = 0; f < 10; f++)
#pragma unroll
        for (int q = 0; q < 4; q++) acc[f][q] = 0.0f;

    uint4 pa[2], pb[5];
#pragma unroll
    for (int j = 0; j < 2; j++)
        pa[j] = *reinterpret_cast<const uint4*>(&g_xh[(size_t)(b0 + arow[j]) * IK + kbase + acol[j] * 8]);
#pragma unroll
    for (int j = 0; j < 5; j++)
        pb[j] = *reinterpret_cast<const uint4*>(&g_A[(size_t)brow[j] * IK + kbase + bcol[j] * 8]);

    for (int st = 0; st < 4; st++) {
        if (st) __syncthreads();
#pragma unroll
        for (int j = 0; j < 2; j++)
            *reinterpret_cast<uint4*>(&Asm[arow[j]][acol[j] * 8]) = pa[j];
#pragma unroll
        for (int j = 0; j < 5; j++)
            *reinterpret_cast<uint4*>(&Bsm[brow[j]][bcol[j] * 8]) = pb[j];
        __syncthreads();
        if (st < 3) {
            int ks = kbase + (st + 1) * 64;
#pragma unroll
            for (int j = 0; j < 2; j++)
                pa[j] = *reinterpret_cast<const uint4*>(&g_xh[(size_t)(b0 + arow[j]) * IK + ks + acol[j] * 8]);
#pragma unroll
            for (int j = 0; j < 5; j++)
                pb[j] = *reinterpret_cast<const uint4*>(&g_A[(size_t)brow[j] * IK + ks + bcol[j] * 8]);
        }
#pragma unroll
        for (int kk = 0; kk < 4; kk++) {
            uint32_t coff = kk * 32;
            uint32_t a[4];
            ldsm_x4(a, aAddr + coff);
#pragma unroll
            for (int f2 = 0; f2 < 5; f2++) {
                uint32_t b[4];
                ldsm_x4(b, bAddr[f2] + coff);
                mma16816(acc[2 * f2],     a[0], a[1], a[2], a[3], b[0], b[1]);
                mma16816(acc[2 * f2 + 1], a[0], a[1], a[2], a[3], b[2], b[3]);
            }
        }
    }
#pragma unroll
    for (int f = 0; f < 10; f++) {
        int no = wn * 80 + f * 8 + 2 * tc;
        int r0 = b0 + wm * 16 + gr;
        *reinterpret_cast<float2*>(&g_sp[kc][(size_t)r0 * NO + no]) =
            make_float2(acc[f][0], acc[f][1]);
        *reinterpret_cast<float2*>(&g_sp[kc][(size_t)(r0 + 8) * NO + no]) =
            make_float2(acc[f][2], acc[f][3]);
    }
}

// ---------------------------------------------------------------------------
// G2: reduce split-K + squash, 4-way parallel over kc. grid 640 x 256.
__global__ __launch_bounds__(256) void k_squash(float* __restrict__ out, int last) {
    __shared__ float red[4][64];
    int t = threadIdx.x;
    int g = t >> 6, sl = t & 63;
    int slot = blockIdx.x * 64 + sl;

    float ps = 0.0f;
#pragma unroll
    for (int q = 0; q < 9; q++) ps += g_sp[g * 9 + q][slot];
    red[g][sl] = ps;
    __syncthreads();

    if (t < 64) {
        float s = (red[0][sl] + red[1][sl]) + (red[2][sl] + red[3][sl]);
        float m = s * s;
        m += __shfl_xor_sync(0xffffffffu, m, 1);
        m += __shfl_xor_sync(0xffffffffu, m, 2);
        m += __shfl_xor_sync(0xffffffffu, m, 4);
        m += __shfl_xor_sync(0xffffffffu, m, 8);
        float v = s * (sqrtf(m) / (1.0f + m));
        if (last) {
            out[slot] = v;
        } else {
            int b = slot / NO, no = slot % NO;
            g_vT[(size_t)no * BB + b] = __float2half_rn(v);
        }
    }
}

// ---------------------------------------------------------------------------
// G3: uv-GEMM + routing update + A-build, pipelined, ldmatrix loads.
// grid 144 (i-chunks of 8), 256 thr. Epilogue uses coalesced WpsT.
__global__ __launch_bounds__(256) void k_uv(int first) {
    __shared__ __half Asm[64][72];
    __shared__ __half Bsm[160][72];
    __shared__ float suv[8][10];
    __shared__ float cs[8][10];
    int t = threadIdx.x;
    int iblk0 = blockIdx.x * 8;
    int ikbase = blockIdx.x * 64;
    int warp = t >> 5, lane = t & 31;
    int wm = warp >> 1, wn = warp & 1;
    int gr = lane >> 2, tc = lane & 3;

    int arow[2], acol[2], brow[5], bcol[5];
#pragma unroll
    for (int j = 0; j < 2; j++) { int s = j * 256 + t; arow[j] = s >> 3; acol[j] = s & 7; }
#pragma unroll
    for (int j = 0; j < 5; j++) { int s = j * 256 + t; brow[j] = s >> 3; bcol[j] = s & 7; }

    int T = lane >> 3, Lr = lane & 7;
    uint32_t aAddr = smem_u32(&Asm[wm * 16 + (T & 1) * 8 + Lr][(T >> 1) * 8]);
    uint32_t bAddr[5];
#pragma unroll
    for (int f2 = 0; f2 < 5; f2++)
        bAddr[f2] = smem_u32(&Bsm[wn * 80 + f2 * 16 + (T >> 1) * 8 + Lr][(T & 1) * 8]);

    float acc[10][4];
#pragma unroll
    for (int f = 0; f < 10; f++)
#pragma unroll
        for (int q = 0; q < 4; q++) acc[f][q] = 0.0f;

    uint4 pa[2], pb[5];
#pragma unroll
    for (int j = 0; j < 2; j++)
        pa[j] = *reinterpret_cast<const uint4*>(&g_xhT[(size_t)(ikbase + arow[j]) * BB + acol[j] * 8]);
#pragma unroll
    for (int j = 0; j < 5; j++)
        pb[j] = *reinterpret_cast<const uint4*>(&g_vT[(size_t)brow[j] * BB + bcol[j] * 8]);

    for (int st = 0; st < 4; st++) {
        if (st) __syncthreads();
#pragma unroll
        for (int j = 0; j < 2; j++)
            *reinterpret_cast<uint4*>(&Asm[arow[j]][acol[j] * 8]) = pa[j];
#pragma unroll
        for (int j = 0; j < 5; j++)
            *reinterpret_cast<uint4*>(&Bsm[brow[j]][bcol[j] * 8]) = pb[j];
        __syncthreads();
        if (st < 3) {
            int bs = (st + 1) * 64;
#pragma unroll
            for (int j = 0; j < 2; j++)
                pa[j] = *reinterpret_cast<const uint4*>(&g_xhT[(size_t)(ikbase + arow[j]) * BB + bs + acol[j] * 8]);
#pragma unroll
            for (int j = 0; j < 5; j++)
                pb[j] = *reinterpret_cast<const uint4*>(&g_vT[(size_t)brow[j] * BB + bs + bcol[j] * 8]);
        }
#pragma unroll
        for (int kk = 0; kk < 4; kk++) {
            uint32_t coff = kk * 32;
            uint32_t a[4];
            ldsm_x4(a, aAddr + coff);
#pragma unroll
            for (int f2 = 0; f2 < 5; f2++) {
                uint32_t b[4];
                ldsm_x4(b, bAddr[f2] + coff);
                mma16816(acc[2 * f2],     a[0], a[1], a[2], a[3], b[0], b[1]);
                mma16816(acc[2 * f2 + 1], a[0], a[1], a[2], a[3], b[2], b[3]);
            }
        }
    }
    __syncthreads();

    // epilogue: weight C frags with WpsT (coalesced float2) -> uv partials
    int i0g = iblk0 + wm * 2;
    int i1g = i0g + 1;
    float p[2][5];
#pragma unroll
    for (int il = 0; il < 2; il++)
#pragma unroll
        for (int nl = 0; nl < 5; nl++) p[il][nl] = 0.0f;

#pragma unroll
    for (int f = 0; f < 10; f++) {
        int no = wn * 80 + f * 8 + 2 * tc;
        float2 wv0 = *reinterpret_cast<const float2*>(&g_WpsT[((size_t)i0g * KK + gr) * NO + no]);
        float2 wv1 = *reinterpret_cast<const float2*>(&g_WpsT[((size_t)i1g * KK + gr) * NO + no]);
        int nl = f >> 1;
        p[0][nl] += acc[f][0] * wv0.x + acc[f][1] * wv0.y;
        p[1][nl] += acc[f][2] * wv1.x + acc[f][3] * wv1.y;
    }
#pragma unroll
    for (int il = 0; il < 2; il++)
#pragma unroll
        for (int nl = 0; nl < 5; nl++) {
            float v = p[il][nl];
#pragma unroll
            for (int off = 16; off > 0; off >>= 1)
                v += __shfl_xor_sync(0xffffffffu, v, off);
            if (lane == 0) suv[wm * 2 + il][wn * 5 + nl] = v;
        }
    __syncthreads();

    if (t < 8) {
        int i = iblk0 + t;
        float bv[NN];
        float mx = -1e30f;
#pragma unroll
        for (int n = 0; n < NN; n++) {
            float bp = first ? 0.0f : g_bij[i * NN + n];
            bv[n] = bp + suv[t][n] * (1.0f / BB);
            g_bij[i * NN + n] = bv[n];
            mx = fmaxf(mx, bv[n]);
        }
        float sum = 0.0f;
#pragma unroll
        for (int n = 0; n < NN; n++) { bv[n] = __expf(bv[n] - mx); sum += bv[n]; }
        float inv = 1.0f / sum;
#pragma unroll
        for (int n = 0; n < NN; n++) cs[t][n] = bv[n] * inv;
    }
    __syncthreads();

    // A-build for this block's i-range: A[no][ikbase..+64) = c[i,n]*Wps
#pragma unroll
    for (int j = 0; j < 20; j++) {
        int s = j * 256 + t;            // 5120 half2 slots
        int no = s >> 5, cp = s & 31;
        int k2 = cp * 2;
        int il = cp >> 2, k = k2 & 7;
        int n = no >> 4, o = no & 15;
        float2 wv = *reinterpret_cast<const float2*>(
            &g_Wps[(((size_t)(iblk0 + il) * NN + n) * OO + o) * KK + k]);
        float cc = cs[il][n];
        __half2 h = __floats2half2_rn(cc * wv.x, cc * wv.y);
        *reinterpret_cast<__half2*>(&g_A[(size_t)no * IK + ikbase + k2]) = h;
    }
}

// ---------------------------------------------------------------------------
extern "C" void kernel_launch(void* const* d_in, const int* in_sizes, int n_in,
                              void* d_out, int out_size) {
    const float* x = (const float*)d_in[0];   // (256, 8, 1152) fp32
    const float* W = (const float*)d_in[1];   // (1, 1152, 10, 16, 8) fp32
    float* out = (float*)d_out;               // (256, 10, 16, 1) fp32

    k_prep<<<288 + (II * NO + 255) / 256, 256>>>(x, W);

    // iter 1 (c = 0.1 baked into A0)
    k_sgemm<<<4 * KC, 256>>>();
    k_squash<<<BB * NO / 64, 256>>>(out, 0);
    k_uv<<<II / 8, 256>>>(1);
    // iter 2
    k_sgemm<<<4 * KC, 256>>>();
    k_squash<<<BB * NO / 64, 256>>>(out, 0);
    k_uv<<<II / 8, 256>>>(0);
    // iter 3
    k_sgemm<<<4 * KC, 256>>>();
    k_squash<<<BB * NO / 64, 256>>>(out, 1);
}

// round 14
// speedup vs baseline: 1.3371x; 1.2515x over previous
#include <cuda_runtime.h>
#include <cuda_fp16.h>
#include <cstdint>

// Problem constants
constexpr int BB = 256;    // batch
constexpr int KK = 8;      // in_size
constexpr int II = 1152;   // in_node_num
constexpr int NN = 10;     // num_node
constexpr int OO = 16;     // node_size
constexpr int IK = II * KK;   // 9216
constexpr int NO = NN * OO;   // 160
constexpr int KC = 36;        // split-K chunks for s-GEMM (9216/256)
constexpr int KCW = IK / KC;  // 256

// Static device scratch (~24 MB total, L2-resident)
__device__ __half g_xh [BB * IK];     // xh[b][i*8+k]
__device__ __half g_xhT[IK * BB];     // xhT[i*8+k][b]
__device__ float  g_Wps[II * NO * KK];// Wps[i][n][o][k] = 0.03*W (fp32, uv epilogue)
__device__ __half g_Wph[NO * IK];     // Wph[n*16+o][i*8+k] = fp16(0.03*W)
__device__ float  g_sp [KC][BB * NO]; // split-K partials
__device__ __half g_vT [NO * BB];     // vT[no][b]
__device__ float  g_bij[II * NN];
__device__ float  g_c  [II * NN];     // routing coefficients

// ---------------------------------------------------------------------------
__device__ __forceinline__ void mma16816(float* c, uint32_t a0, uint32_t a1,
                                         uint32_t a2, uint32_t a3,
                                         uint32_t b0, uint32_t b1) {
    asm volatile(
        "mma.sync.aligned.m16n8k16.row.col.f32.f16.f16.f32 "
        "{%0,%1,%2,%3}, {%4,%5,%6,%7}, {%8,%9}, {%0,%1,%2,%3};"
        : "+f"(c[0]), "+f"(c[1]), "+f"(c[2]), "+f"(c[3])
        : "r"(a0), "r"(a1), "r"(a2), "r"(a3), "r"(b0), "r"(b1));
}

__device__ __forceinline__ void ldsm_x4(uint32_t* r, uint32_t addr) {
    asm volatile(
        "ldmatrix.sync.aligned.m8n8.x4.shared.b16 {%0,%1,%2,%3}, [%4];"
        : "=r"(r[0]), "=r"(r[1]), "=r"(r[2]), "=r"(r[3]) : "r"(addr));
}

__device__ __forceinline__ uint32_t smem_u32(const void* p) {
    return (uint32_t)__cvta_generic_to_shared(p);
}

// ---------------------------------------------------------------------------
// P: fused prep. Blocks [0,288): pack x -> xh, xhT. Blocks [288,1008): Wps/Wph.
__global__ __launch_bounds__(256) void k_prep(const float* __restrict__ x,
                                              const float* __restrict__ W) {
    __shared__ float tf[32][32][9];   // [b][i][k], pad 9
    int t = threadIdx.x;
    if (blockIdx.x < 288) {
        int tile = blockIdx.x;
        int i0 = (tile % 36) * 32, b0 = (tile / 36) * 32;
        int kk = t >> 5, il = t & 31;
#pragma unroll
        for (int j = 0; j < 32; j++)
            tf[j][il][kk] = x[((size_t)(b0 + j) * KK + kk) * II + i0 + il];
        __syncthreads();
#pragma unroll
        for (int jj = 0; jj < 4; jj++) {
            int s = jj * 256 + t;
            int bl = s >> 5, u = s & 31;
            __half h[8];
#pragma unroll
            for (int k = 0; k < 8; k++) h[k] = __float2half_rn(tf[bl][u][k]);
            *reinterpret_cast<uint4*>(&g_xh[(size_t)(b0 + bl) * IK + (i0 + u) * 8]) =
                *reinterpret_cast<const uint4*>(h);
        }
#pragma unroll
        for (int jj = 0; jj < 4; jj++) {
            int s = jj * 256 + t;
            int row = s >> 2, w = s & 3;
            int il2 = row >> 3, k = row & 7;
            __half h[8];
#pragma unroll
            for (int bb = 0; bb < 8; bb++) h[bb] = __float2half_rn(tf[w * 8 + bb][il2][k]);
            *reinterpret_cast<uint4*>(&g_xhT[(size_t)((i0 + il2) * 8 + k) * BB + b0 + w * 8]) =
                *reinterpret_cast<const uint4*>(h);
        }
    } else {
        int tid = (blockIdx.x - 288) * 256 + t;   // (i*160 + no)
        if (tid >= II * NO) return;
        int i = tid / NO, no = tid % NO;
        float4 w0 = *reinterpret_cast<const float4*>(&W[(size_t)tid * 8]);
        float4 w1 = *reinterpret_cast<const float4*>(&W[(size_t)tid * 8 + 4]);
        float s = 0.03f;
        float p[8] = { s*w0.x, s*w0.y, s*w0.z, s*w0.w, s*w1.x, s*w1.y, s*w1.z, s*w1.w };
        *reinterpret_cast<float4*>(&g_Wps[(size_t)tid * 8])     = make_float4(p[0], p[1], p[2], p[3]);
        *reinterpret_cast<float4*>(&g_Wps[(size_t)tid * 8 + 4]) = make_float4(p[4], p[5], p[6], p[7]);
        __half h[8];
#pragma unroll
        for (int k = 0; k < 8; k++) h[k] = __float2half_rn(p[k]);
        *reinterpret_cast<uint4*>(&g_Wph[(size_t)no * IK + i * 8]) =
            *reinterpret_cast<const uint4*>(h);
    }
}

// ---------------------------------------------------------------------------
// G1: s-GEMM, split-K, pipelined, ldmatrix. B = c .* Wph staged on the fly.
// grid 144 = 4 b-tiles(64) x 36 kc. 8 warps (4x2).
__global__ __launch_bounds__(256) void k_sgemm(int use_const) {
    __shared__ __half Asm[64][72];
    __shared__ __half Bsm[160][72];
    int t = threadIdx.x;
    int bm = blockIdx.x & 3, kc = blockIdx.x >> 2;
    int b0 = bm * 64, kbase = kc * KCW;
    int warp = t >> 5, lane = t & 31;
    int wm = warp >> 1, wn = warp & 1;
    int gr = lane >> 2, tc = lane & 3;

    int arow[2], acol[2], brow[5], bcol[5];
#pragma unroll
    for (int j = 0; j < 2; j++) { int s = j * 256 + t; arow[j] = s >> 3; acol[j] = s & 7; }
#pragma unroll
    for (int j = 0; j < 5; j++) { int s = j * 256 + t; brow[j] = s >> 3; bcol[j] = s & 7; }

    int T = lane >> 3, Lr = lane & 7;
    uint32_t aAddr = smem_u32(&Asm[wm * 16 + (T & 1) * 8 + Lr][(T >> 1) * 8]);
    uint32_t bAddr[5];
#pragma unroll
    for (int f2 = 0; f2 < 5; f2++)
        bAddr[f2] = smem_u32(&Bsm[wn * 80 + f2 * 16 + (T >> 1) * 8 + Lr][(T & 1) * 8]);

    float acc[10][4];
#pragma unroll
    for (int f = 0; f < 10; f++)
#pragma unroll
        for (int q = 0; q < 4; q++) acc[f][q] = 0.0f;

    const __half2 cconst = __floats2half2_rn(0.1f, 0.1f);

    uint4 pa[2], pb[5];
    float pc[5];
#pragma unroll
    for (int j = 0; j < 2; j++)
        pa[j] = *reinterpret_cast<const uint4*>(&g_xh[(size_t)(b0 + arow[j]) * IK + kbase + acol[j] * 8]);
#pragma unroll
    for (int j = 0; j < 5; j++) {
        pb[j] = *reinterpret_cast<const uint4*>(&g_Wph[(size_t)brow[j] * IK + kbase + bcol[j] * 8]);
        if (!use_const)
            pc[j] = g_c[(kbase / 8 + bcol[j]) * NN + (brow[j] >> 4)];
    }

    for (int st = 0; st < 4; st++) {
        if (st) __syncthreads();
#pragma unroll
        for (int j = 0; j < 2; j++)
            *reinterpret_cast<uint4*>(&Asm[arow[j]][acol[j] * 8]) = pa[j];
#pragma unroll
        for (int j = 0; j < 5; j++) {
            __half2 cc2 = use_const ? cconst : __floats2half2_rn(pc[j], pc[j]);
            const __half2* hp = reinterpret_cast<const __half2*>(&pb[j]);
            uint4 v;
            __half2* vp = reinterpret_cast<__half2*>(&v);
            vp[0] = __hmul2(hp[0], cc2);
            vp[1] = __hmul2(hp[1], cc2);
            vp[2] = __hmul2(hp[2], cc2);
            vp[3] = __hmul2(hp[3], cc2);
            *reinterpret_cast<uint4*>(&Bsm[brow[j]][bcol[j] * 8]) = v;
        }
        __syncthreads();
        if (st < 3) {
            int ks = kbase + (st + 1) * 64;
#pragma unroll
            for (int j = 0; j < 2; j++)
                pa[j] = *reinterpret_cast<const uint4*>(&g_xh[(size_t)(b0 + arow[j]) * IK + ks + acol[j] * 8]);
#pragma unroll
            for (int j = 0; j < 5; j++) {
                pb[j] = *reinterpret_cast<const uint4*>(&g_Wph[(size_t)brow[j] * IK + ks + bcol[j] * 8]);
                if (!use_const)
                    pc[j] = g_c[(ks / 8 + bcol[j]) * NN + (brow[j] >> 4)];
            }
        }
#pragma unroll
        for (int kk = 0; kk < 4; kk++) {
            uint32_t coff = kk * 32;
            uint32_t a[4];
            ldsm_x4(a, aAddr + coff);
#pragma unroll
            for (int f2 = 0; f2 < 5; f2++) {
                uint32_t b[4];
                ldsm_x4(b, bAddr[f2] + coff);
                mma16816(acc[2 * f2],     a[0], a[1], a[2], a[3], b[0], b[1]);
                mma16816(acc[2 * f2 + 1], a[0], a[1], a[2], a[3], b[2], b[3]);
            }
        }
    }
#pragma unroll
    for (int f = 0; f < 10; f++) {
        int no = wn * 80 + f * 8 + 2 * tc;
        int r0 = b0 + wm * 16 + gr;
        *reinterpret_cast<float2*>(&g_sp[kc][(size_t)r0 * NO + no]) =
            make_float2(acc[f][0], acc[f][1]);
        *reinterpret_cast<float2*>(&g_sp[kc][(size_t)(r0 + 8) * NO + no]) =
            make_float2(acc[f][2], acc[f][3]);
    }
}

// ---------------------------------------------------------------------------
// G2: reduce split-K + squash, 4-way parallel over kc. grid 640 x 256.
__global__ __launch_bounds__(256) void k_squash(float* __restrict__ out, int last) {
    __shared__ float red[4][64];
    int t = threadIdx.x;
    int g = t >> 6, sl = t & 63;
    int slot = blockIdx.x * 64 + sl;

    float ps = 0.0f;
#pragma unroll
    for (int q = 0; q < 9; q++) ps += g_sp[g * 9 + q][slot];
    red[g][sl] = ps;
    __syncthreads();

    if (t < 64) {
        float s = (red[0][sl] + red[1][sl]) + (red[2][sl] + red[3][sl]);
        float m = s * s;
        m += __shfl_xor_sync(0xffffffffu, m, 1);
        m += __shfl_xor_sync(0xffffffffu, m, 2);
        m += __shfl_xor_sync(0xffffffffu, m, 4);
        m += __shfl_xor_sync(0xffffffffu, m, 8);
        float v = s * (sqrtf(m) / (1.0f + m));
        if (last) {
            out[slot] = v;
        } else {
            int b = slot / NO, no = slot % NO;
            g_vT[(size_t)no * BB + b] = __float2half_rn(v);
        }
    }
}

// ---------------------------------------------------------------------------
// G3: uv-GEMM + routing update (writes g_c; no A-build). grid 144, 256 thr.
__global__ __launch_bounds__(256) void k_uv(int first) {
    __shared__ __half Asm[64][72];
    __shared__ __half Bsm[160][72];
    __shared__ float suv[8][10];
    int t = threadIdx.x;
    int iblk0 = blockIdx.x * 8;
    int ikbase = blockIdx.x * 64;
    int warp = t >> 5, lane = t & 31;
    int wm = warp >> 1, wn = warp & 1;
    int gr = lane >> 2, tc = lane & 3;

    int arow[2], acol[2], brow[5], bcol[5];
#pragma unroll
    for (int j = 0; j < 2; j++) { int s = j * 256 + t; arow[j] = s >> 3; acol[j] = s & 7; }
#pragma unroll
    for (int j = 0; j < 5; j++) { int s = j * 256 + t; brow[j] = s >> 3; bcol[j] = s & 7; }

    int T = lane >> 3, Lr = lane & 7;
    uint32_t aAddr = smem_u32(&Asm[wm * 16 + (T & 1) * 8 + Lr][(T >> 1) * 8]);
    uint32_t bAddr[5];
#pragma unroll
    for (int f2 = 0; f2 < 5; f2++)
        bAddr[f2] = smem_u32(&Bsm[wn * 80 + f2 * 16 + (T >> 1) * 8 + Lr][(T & 1) * 8]);

    float acc[10][4];
#pragma unroll
    for (int f = 0; f < 10; f++)
#pragma unroll
        for (int q = 0; q < 4; q++) acc[f][q] = 0.0f;

    uint4 pa[2], pb[5];
#pragma unroll
    for (int j = 0; j < 2; j++)
        pa[j] = *reinterpret_cast<const uint4*>(&g_xhT[(size_t)(ikbase + arow[j]) * BB + acol[j] * 8]);
#pragma unroll
    for (int j = 0; j < 5; j++)
        pb[j] = *reinterpret_cast<const uint4*>(&g_vT[(size_t)brow[j] * BB + bcol[j] * 8]);

    for (int st = 0; st < 4; st++) {
        if (st) __syncthreads();
#pragma unroll
        for (int j = 0; j < 2; j++)
            *reinterpret_cast<uint4*>(&Asm[arow[j]][acol[j] * 8]) = pa[j];
#pragma unroll
        for (int j = 0; j < 5; j++)
            *reinterpret_cast<uint4*>(&Bsm[brow[j]][bcol[j] * 8]) = pb[j];
        __syncthreads();
        if (st < 3) {
            int bs = (st + 1) * 64;
#pragma unroll
            for (int j = 0; j < 2; j++)
                pa[j] = *reinterpret_cast<const uint4*>(&g_xhT[(size_t)(ikbase + arow[j]) * BB + bs + acol[j] * 8]);
#pragma unroll
            for (int j = 0; j < 5; j++)
                pb[j] = *reinterpret_cast<const uint4*>(&g_vT[(size_t)brow[j] * BB + bs + bcol[j] * 8]);
        }
#pragma unroll
        for (int kk = 0; kk < 4; kk++) {
            uint32_t coff = kk * 32;
            uint32_t a[4];
            ldsm_x4(a, aAddr + coff);
#pragma unroll
            for (int f2 = 0; f2 < 5; f2++) {
                uint32_t b[4];
                ldsm_x4(b, bAddr[f2] + coff);
                mma16816(acc[2 * f2],     a[0], a[1], a[2], a[3], b[0], b[1]);
                mma16816(acc[2 * f2 + 1], a[0], a[1], a[2], a[3], b[2], b[3]);
            }
        }
    }
    __syncthreads();

    // epilogue: weight C frags with Wps and reduce over (k,o) -> uv partials
    int i0g = iblk0 + wm * 2;
    int i1g = i0g + 1;
    float p[2][5];
#pragma unroll
    for (int il = 0; il < 2; il++)
#pragma unroll
        for (int nl = 0; nl < 5; nl++) p[il][nl] = 0.0f;

#pragma unroll
    for (int f = 0; f < 10; f++) {
        int no = wn * 80 + f * 8 + 2 * tc;
        int n = no >> 4, o = no & 15;
        float w00 = g_Wps[(((size_t)i0g * NN + n) * OO + o) * KK + gr];
        float w01 = g_Wps[(((size_t)i0g * NN + n) * OO + o + 1) * KK + gr];
        float w10 = g_Wps[(((size_t)i1g * NN + n) * OO + o) * KK + gr];
        float w11 = g_Wps[(((size_t)i1g * NN + n) * OO + o + 1) * KK + gr];
        int nl = f >> 1;
        p[0][nl] += acc[f][0] * w00 + acc[f][1] * w01;
        p[1][nl] += acc[f][2] * w10 + acc[f][3] * w11;
    }
#pragma unroll
    for (int il = 0; il < 2; il++)
#pragma unroll
        for (int nl = 0; nl < 5; nl++) {
            float v = p[il][nl];
#pragma unroll
            for (int off = 16; off > 0; off >>= 1)
                v += __shfl_xor_sync(0xffffffffu, v, off);
            if (lane == 0) suv[wm * 2 + il][wn * 5 + nl] = v;
        }
    __syncthreads();

    if (t < 8) {
        int i = iblk0 + t;
        float bv[NN];
        float mx = -1e30f;
#pragma unroll
        for (int n = 0; n < NN; n++) {
            float bp = first ? 0.0f : g_bij[i * NN + n];
            bv[n] = bp + suv[t][n] * (1.0f / BB);
            g_bij[i * NN + n] = bv[n];
            mx = fmaxf(mx, bv[n]);
        }
        float sum = 0.0f;
#pragma unroll
        for (int n = 0; n < NN; n++) { bv[n] = __expf(bv[n] - mx); sum += bv[n]; }
        float inv = 1.0f / sum;
#pragma unroll
        for (int n = 0; n < NN; n++) g_c[i * NN + n] = bv[n] * inv;
    }
}

// ---------------------------------------------------------------------------
extern "C" void kernel_launch(void* const* d_in, const int* in_sizes, int n_in,
                              void* d_out, int out_size) {
    const float* x = (const float*)d_in[0];   // (256, 8, 1152) fp32
    const float* W = (const float*)d_in[1];   // (1, 1152, 10, 16, 8) fp32
    float* out = (float*)d_out;               // (256, 10, 16, 1) fp32

    k_prep<<<288 + (II * NO + 255) / 256, 256>>>(x, W);

    // iter 1 (c = 0.1 constant)
    k_sgemm<<<4 * KC, 256>>>(1);
    k_squash<<<BB * NO / 64, 256>>>(out, 0);
    k_uv<<<II / 8, 256>>>(1);
    // iter 2
    k_sgemm<<<4 * KC, 256>>>(0);
    k_squash<<<BB * NO / 64, 256>>>(out, 0);
    k_uv<<<II / 8, 256>>>(0);
    // iter 3
    k_sgemm<<<4 * KC, 256>>>(0);
    k_squash<<<BB * NO / 64, 256>>>(out, 1);
}